// round 1
// baseline (speedup 1.0000x reference)
#include <cuda_runtime.h>

#define IN_DIM  8192
#define OUT_DIM 8192
#define TPB     256
#define THRESH  50.0f

__global__ __launch_bounds__(TPB, 4)
void snn_fused_kernel(const float* __restrict__ spike_input,
                      const float* __restrict__ states,
                      const float* __restrict__ v_mem,
                      const float* __restrict__ v_th,
                      const float* __restrict__ elig,
                      const float* __restrict__ noise,
                      float* __restrict__ out)
{
    __shared__ float s_spike[IN_DIM];        // 32 KB: spike_input staged once
    __shared__ float s_warp[TPB / 32];
    __shared__ float s_spk_bcast;

    const int row = blockIdx.x;
    const int tid = threadIdx.x;

    // ---- stage spike_input into shared (vectorized) ----
    const float4* sp4 = reinterpret_cast<const float4*>(spike_input);
    float4* ss4 = reinterpret_cast<float4*>(s_spike);
    #pragma unroll
    for (int it = 0; it < IN_DIM / 4 / TPB; ++it)
        ss4[it * TPB + tid] = sp4[it * TPB + tid];
    __syncthreads();

    // ---- phase 1: binary-weight GEMV row dot product ----
    const float4* st4 = reinterpret_cast<const float4*>(states + (size_t)row * IN_DIM);
    float acc = 0.0f;
    #pragma unroll
    for (int it = 0; it < IN_DIM / 4 / TPB; ++it) {
        const int i = it * TPB + tid;
        float4 s  = st4[i];
        float4 sp = ss4[i];
        // w = (state > 50) ? 1 : 0 ; acc += w * spike (spike is 0/1)
        if (s.x > THRESH) acc += sp.x;
        if (s.y > THRESH) acc += sp.y;
        if (s.z > THRESH) acc += sp.z;
        if (s.w > THRESH) acc += sp.w;
    }

    // warp reduce
    #pragma unroll
    for (int off = 16; off > 0; off >>= 1)
        acc += __shfl_xor_sync(0xFFFFFFFFu, acc, off);
    if ((tid & 31) == 0) s_warp[tid >> 5] = acc;
    __syncthreads();

    // ---- per-row scalar dynamics (thread 0) ----
    if (tid == 0) {
        float total = 0.0f;
        #pragma unroll
        for (int w = 0; w < TPB / 32; ++w) total += s_warp[w];

        const float vth   = v_th[row];
        const float v_new = v_mem[row] * 0.8f + total + noise[row];
        const float spk   = (v_new >= vth) ? 1.0f : 0.0f;

        // outputs: [spikes | v_mem_new | v_th_new | elig_new]
        out[row]               = spk;
        out[OUT_DIM + row]     = v_new * (1.0f - spk) * 0.2f;
        float vth_new = vth + (spk - 0.05f) * 0.1f;
        vth_new = fminf(fmaxf(vth_new, 0.5f), 10.0f);
        out[2 * OUT_DIM + row] = vth_new;

        s_spk_bcast = spk;
    }
    __syncthreads();

    // ---- phase 2: eligibility trace row update ----
    const float spk = s_spk_bcast;
    const float4* el4 = reinterpret_cast<const float4*>(elig + (size_t)row * IN_DIM);
    float4* out4 = reinterpret_cast<float4*>(out + 3 * (size_t)OUT_DIM + (size_t)row * IN_DIM);
    #pragma unroll
    for (int it = 0; it < IN_DIM / 4 / TPB; ++it) {
        const int i = it * TPB + tid;
        float4 e  = el4[i];
        float4 sp = ss4[i];
        e.x = fminf(fmaxf(fmaf(e.x, 0.95f, spk * sp.x), 0.0f), 5.0f);
        e.y = fminf(fmaxf(fmaf(e.y, 0.95f, spk * sp.y), 0.0f), 5.0f);
        e.z = fminf(fmaxf(fmaf(e.z, 0.95f, spk * sp.z), 0.0f), 5.0f);
        e.w = fminf(fmaxf(fmaf(e.w, 0.95f, spk * sp.w), 0.0f), 5.0f);
        out4[i] = e;
    }
}

extern "C" void kernel_launch(void* const* d_in, const int* in_sizes, int n_in,
                              void* d_out, int out_size)
{
    const float* spike_input = (const float*)d_in[0];
    const float* states      = (const float*)d_in[1];
    const float* v_mem       = (const float*)d_in[2];
    const float* v_th        = (const float*)d_in[3];
    const float* elig        = (const float*)d_in[4];
    const float* noise       = (const float*)d_in[5];
    float* out = (float*)d_out;

    snn_fused_kernel<<<OUT_DIM, TPB>>>(spike_input, states, v_mem, v_th,
                                       elig, noise, out);
}